// round 13
// baseline (speedup 1.0000x reference)
#include <cuda_runtime.h>
#include <cstdint>

#define DD 1024
#define BATCH 64
#define TT 200
#define TB (TT*BATCH)
#define NCTA 128
#define ASTRIDE 132

typedef unsigned long long ull;

// ---------------- scratch (static __device__, no allocations) ----------------
__device__ float g_xT[TB*DD];     // x transposed: [t][b][k]
__device__ float g_WX[TB*DD];     // wx for all timesteps
__device__ float g_H [TB*DD];     // h_t for all timesteps
__device__ float g_Y [TB*DD];     // y before final transpose
__device__ float g_A0[BATCH*DD];  // h+h0  (GEMM input P1)
__device__ float g_A1[BATCH*DD];  // F1    (GEMM input P2)
__device__ float g_A2[BATCH*DD];  // T2    (GEMM input P3)
__device__ unsigned g_bar_count;
__device__ volatile unsigned g_bar_gen;

// ---------------- helpers ----------------
__device__ __forceinline__ void ffma2(ull& d, ull a, ull b) {
    asm("fma.rn.f32x2 %0, %1, %2, %0;" : "+l"(d) : "l"(a), "l"(b));
}
__device__ __forceinline__ float hsum2(ull v) {
    float lo, hi;
    asm("mov.b64 {%0,%1}, %2;" : "=f"(lo), "=f"(hi) : "l"(v));
    return lo + hi;
}
__device__ __forceinline__ float elu_f(float x) { return x > 0.f ? x : expm1f(x); }

__device__ __forceinline__ void cp16(float* dst_smem, const float* src) {
    unsigned s = (unsigned)__cvta_generic_to_shared(dst_smem);
    asm volatile("cp.async.cg.shared.global [%0], [%1], 16;" :: "r"(s), "l"(src));
}
__device__ __forceinline__ void cp_commit() {
    asm volatile("cp.async.commit_group;");
}

__device__ __forceinline__ void grid_sync() {
    __syncthreads();
    if (threadIdx.x == 0) {
        unsigned gen = g_bar_gen;
        __threadfence();
        if (atomicAdd(&g_bar_count, 1) == gridDim.x - 1) {
            g_bar_count = 0;
            __threadfence();
            g_bar_gen = gen + 1;
        } else {
            while (g_bar_gen == gen) { __nanosleep(32); }
            __threadfence();
        }
    }
    __syncthreads();
}

// ---------------- seq smem layout (floats) ----------------
#define SW_FLOATS   8192              // per matrix: float2[(c*64+kp)*8+n]
#define SA_FLOATS   (64*ASTRIDE)      // 8448 per buffer
#define RED_STRIDE  68
#define OFF_SA      (3*SW_FLOATS)                 // 24576
#define OFF_RED     (OFF_SA + 2*SA_FLOATS)        // 41472
#define OFF_H       (OFF_RED + 64*RED_STRIDE)     // 45824
#define SEQ_FLOATS  (OFF_H + 3*512)               // 47360
#define SEQ_BYTES   (SEQ_FLOATS*4)                // 189440

// ---------------- sequential-phase GEMM core ----------------
// C[64][8] = A[64][1024] @ Wslice[8][1024]^T.
// Thread tile: Tm=8 (rows i*8+mg), Tn=8 (all n), k-split 32 (warp*4+kss), K_t=32.
// Returns raw dot products for outputs o=tid*2 (.x) and o=tid*2+1 (.y).
__device__ __noinline__ float2 mm_phase(const float* __restrict__ Ag,
                                        const float2* __restrict__ sWm,
                                        float* __restrict__ sA,
                                        float* __restrict__ red)
{
    const int tid  = threadIdx.x;
    const int warp = tid >> 5, lane = tid & 31;
    const int mg = lane & 7, kss = lane >> 3;
    const int kc = (warp*4 + kss)*4;           // float offset within 128-chunk

    ull acc[8][8];
    #pragma unroll
    for (int i = 0; i < 8; i++)
        #pragma unroll
        for (int n = 0; n < 8; n++) acc[i][n] = 0ull;

    // stage chunk 0: id = s*256+tid; row=id>>5, u=id&31 (16B units)
    #pragma unroll
    for (int s = 0; s < 8; s++) {
        const int id = s*256 + tid, row = id >> 5, u = id & 31;
        cp16(sA + row*ASTRIDE + u*4, Ag + row*DD + u*4);
    }
    cp_commit();

    #pragma unroll 1
    for (int c = 0; c < 8; c++) {
        if (c < 7) {
            float* dst = sA + ((c+1) & 1) * SA_FLOATS;
            const float* src = Ag + (c+1)*128;
            #pragma unroll
            for (int s = 0; s < 8; s++) {
                const int id = s*256 + tid, row = id >> 5, u = id & 31;
                cp16(dst + row*ASTRIDE + u*4, src + row*DD + u*4);
            }
            cp_commit();
            asm volatile("cp.async.wait_group 1;");
        } else {
            asm volatile("cp.async.wait_group 0;");
        }
        __syncthreads();

        const float* sAb = sA + (c & 1) * SA_FLOATS;
        ulonglong2 av[8];
        #pragma unroll
        for (int i = 0; i < 8; i++)
            av[i] = *(const ulonglong2*)(sAb + (i*8 + mg)*ASTRIDE + kc);

        const int kp0 = (c*64) + warp*8 + kss*2;
        const ulonglong2* wb0 = (const ulonglong2*)(sWm + kp0*8);
        const ulonglong2* wb1 = (const ulonglong2*)(sWm + (kp0+1)*8);
        ulonglong2 w0[4], w1[4];
        #pragma unroll
        for (int np = 0; np < 4; np++) { w0[np] = wb0[np]; w1[np] = wb1[np]; }

        #pragma unroll
        for (int i = 0; i < 8; i++)
            #pragma unroll
            for (int np = 0; np < 4; np++) {
                ffma2(acc[i][np*2],   av[i].x, w0[np].x);
                ffma2(acc[i][np*2],   av[i].y, w1[np].x);
                ffma2(acc[i][np*2+1], av[i].x, w0[np].y);
                ffma2(acc[i][np*2+1], av[i].y, w1[np].y);
            }
        __syncthreads();
    }

    // reduce across kss (intra-warp shfl), then across warps (smem)
    float v[64];
    #pragma unroll
    for (int i = 0; i < 8; i++)
        #pragma unroll
        for (int n = 0; n < 8; n++) v[i*8+n] = hsum2(acc[i][n]);
    #pragma unroll
    for (int e = 0; e < 64; e++) {
        v[e] += __shfl_xor_sync(0xffffffffu, v[e], 8);
        v[e] += __shfl_xor_sync(0xffffffffu, v[e], 16);
    }
    if (lane < 8) {
        float* r = red + (warp*8 + mg)*RED_STRIDE;
        #pragma unroll
        for (int i = 0; i < 8; i++) {
            *(float4*)&r[i*8]     = make_float4(v[i*8],   v[i*8+1], v[i*8+2], v[i*8+3]);
            *(float4*)&r[i*8 + 4] = make_float4(v[i*8+4], v[i*8+5], v[i*8+6], v[i*8+7]);
        }
    }
    __syncthreads();

    float2 out;
    {
        const int o0 = tid*2;
        const int m0 = o0 >> 3, n0 = o0 & 7;
        const int m1 = (o0+1) >> 3, n1 = (o0+1) & 7;
        float s0 = 0.f, s1 = 0.f;
        #pragma unroll
        for (int w = 0; w < 8; w++) {
            s0 += red[(w*8 + (m0 & 7))*RED_STRIDE + (m0 >> 3)*8 + n0];
            s1 += red[(w*8 + (m1 & 7))*RED_STRIDE + (m1 >> 3)*8 + n1];
        }
        out.x = s0; out.y = s1;
    }
    __syncthreads();
    return out;
}

// ---------------- persistent sequential kernel ----------------
__global__ void __launch_bounds__(256, 1) ernn_seq(
    const float* __restrict__ Whid, const float* __restrict__ bhid,
    const float* __restrict__ Wm2,  const float* __restrict__ b2,
    const float* __restrict__ Wm3,  const float* __restrict__ b3,
    const float* __restrict__ etas)
{
    extern __shared__ float sm[];
    float2* sW1 = (float2*)(sm);
    float2* sW2 = (float2*)(sm + SW_FLOATS);
    float2* sW3 = (float2*)(sm + 2*SW_FLOATS);
    float*  sA  = sm + OFF_SA;
    float*  red = sm + OFF_RED;
    float*  sh_h  = sm + OFF_H;
    float*  sh_h0 = sh_h + 512;
    float*  sh_hp = sh_h0 + 512;

    const int tid   = threadIdx.x;
    const int nbase = blockIdx.x * 8;

    // preload W slices into interleaved float2 layout: sW[j*8+n] = W[nbase+n][2j..2j+1]
    #pragma unroll 1
    for (int n = 0; n < 8; n++) {
        const float2* Wr1 = (const float2*)&Whid[(size_t)(nbase+n)*DD];
        const float2* Wr2 = (const float2*)&Wm2 [(size_t)(nbase+n)*DD];
        const float2* Wr3 = (const float2*)&Wm3 [(size_t)(nbase+n)*DD];
        for (int j = tid; j < 512; j += 256) {
            sW1[j*8 + n] = __ldg(&Wr1[j]);
            sW2[j*8 + n] = __ldg(&Wr2[j]);
            sW3[j*8 + n] = __ldg(&Wr3[j]);
        }
    }
    // zero state + own columns of g_A0
    for (int o = tid; o < 512; o += 256) {
        sh_h[o] = 0.f; sh_h0[o] = 0.f; sh_hp[o] = 0.f;
        const int m = o >> 3, n = o & 7;
        g_A0[m*DD + nbase + n] = 0.f;
    }
    grid_sync();

    // per-thread epilogue constants (thread owns outputs o0, o0+1)
    const int o0 = tid*2;
    const int m0 = o0 >> 3,     n0 = o0 & 7;
    const int m1 = (o0+1) >> 3, n1 = (o0+1) & 7;
    const float bh0 = __ldg(&bhid[nbase+n0]), bh1 = __ldg(&bhid[nbase+n1]);
    const float b20 = __ldg(&b2[nbase+n0]),   b21 = __ldg(&b2[nbase+n1]);
    const float b30 = __ldg(&b3[nbase+n0]),   b31 = __ldg(&b3[nbase+n1]);
    float e5[5];
    #pragma unroll
    for (int k = 0; k < 5; k++) e5[k] = __ldg(&etas[k]);

    #pragma unroll 1
    for (int t = 0; t < TT; t++) {
        const float* wxt = g_WX + (size_t)t * BATCH * DD;
        #pragma unroll 1
        for (int it = 0; it < 5; it++) {
            // ---- P1: F1 = elu((h+h0)@Whid^T + bhid + wx) ----
            float2 r = mm_phase(g_A0, sW1, sA, red);
            {
                float s0 = r.x + bh0 + __ldg(&wxt[m0*DD + nbase + n0]);
                float s1 = r.y + bh1 + __ldg(&wxt[m1*DD + nbase + n1]);
                __stcg(&g_A1[m0*DD + nbase + n0], elu_f(s0));
                __stcg(&g_A1[m1*DD + nbase + n1], elu_f(s1));
            }
            grid_sync();

            // ---- P2: T2 = elu(F1@W2^T + b2) ----
            r = mm_phase(g_A1, sW2, sA, red);
            __stcg(&g_A2[m0*DD + nbase + n0], elu_f(r.x + b20));
            __stcg(&g_A2[m1*DD + nbase + n1], elu_f(r.y + b21));
            grid_sync();

            // ---- P3: Fn = elu(T2@W3^T + b3); state update ----
            r = mm_phase(g_A2, sW3, sA, red);
            {
                const float eta = e5[it];
                const float fn0 = elu_f(r.x + b30);
                const float fn1 = elu_f(r.y + b31);
                const float h0n = sh_h[o0]   + eta * (fn0 - sh_hp[o0]);
                const float h1n = sh_h[o0+1] + eta * (fn1 - sh_hp[o0+1]);
                sh_h[o0] = h0n; sh_h[o0+1] = h1n;
                float hp0, hp1;
                if (it == 4) {
                    sh_h0[o0] = h0n; sh_h0[o0+1] = h1n;
                    hp0 = 2.f*h0n; hp1 = 2.f*h1n;
                    g_H[((size_t)t*BATCH + m0)*DD + nbase + n0] = h0n;
                    g_H[((size_t)t*BATCH + m1)*DD + nbase + n1] = h1n;
                } else {
                    hp0 = h0n + sh_h0[o0]; hp1 = h1n + sh_h0[o0+1];
                }
                sh_hp[o0] = hp0; sh_hp[o0+1] = hp1;
                __stcg(&g_A0[m0*DD + nbase + n0], hp0);
                __stcg(&g_A0[m1*DD + nbase + n1], hp1);
            }
            grid_sync();
        }
    }
}

// ---------------- parallel tiled GEMM: C = A @ W^T + bias ----------------
#define PAR_SMEM_BYTES (2*64*ASTRIDE*4)

__global__ void __launch_bounds__(256, 1) gemm64(const float* __restrict__ A,
                                                 const float* __restrict__ Wm,
                                                 const float* __restrict__ bias,
                                                 float* __restrict__ C)
{
    extern __shared__ float smp[];
    float* sA = smp;
    float* sB = smp + 64*ASTRIDE;

    const int tid  = threadIdx.x;
    const int warp = tid >> 5, lane = tid & 31;
    const int mh = warp & 1, nq = warp >> 1;
    const int mlane = lane >> 2, nlane = lane & 3;
    const int mbase = blockIdx.y * 64, nbase = blockIdx.x * 64;

    ull acc[4][4];
    #pragma unroll
    for (int i = 0; i < 4; i++)
        #pragma unroll
        for (int j = 0; j < 4; j++) acc[i][j] = 0ull;

    #pragma unroll 1
    for (int c = 0; c < 8; c++) {
        if (c) __syncthreads();
        #pragma unroll
        for (int p = 0; p < 8; p++) {
            const int row = p*8 + warp;
            *(ulonglong2*)&sA[row*ASTRIDE + lane*4] =
                __ldg((const ulonglong2*)(A  + (size_t)(mbase+row)*DD + c*128 + lane*4));
            *(ulonglong2*)&sB[row*ASTRIDE + lane*4] =
                __ldg((const ulonglong2*)(Wm + (size_t)(nbase+row)*DD + c*128 + lane*4));
        }
        __syncthreads();
        #pragma unroll 4
        for (int q = 0; q < 32; q++) {
            const int k0 = q*4;
            ulonglong2 a[4], w[4];
            #pragma unroll
            for (int i = 0; i < 4; i++)
                a[i] = *(const ulonglong2*)&sA[(mh*32 + i*8 + mlane)*ASTRIDE + k0];
            #pragma unroll
            for (int j = 0; j < 4; j++)
                w[j] = *(const ulonglong2*)&sB[(nq*16 + j*4 + nlane)*ASTRIDE + k0];
            #pragma unroll
            for (int i = 0; i < 4; i++)
                #pragma unroll
                for (int j = 0; j < 4; j++) {
                    ffma2(acc[i][j], a[i].x, w[j].x);
                    ffma2(acc[i][j], a[i].y, w[j].y);
                }
        }
    }
    #pragma unroll
    for (int i = 0; i < 4; i++)
        #pragma unroll
        for (int j = 0; j < 4; j++) {
            const int m = mbase + mh*32 + i*8 + mlane;
            const int n = nbase + nq*16 + j*4 + nlane;
            C[(size_t)m*DD + n] = hsum2(acc[i][j]) + __ldg(&bias[n]);
        }
}

// ---------------- transposes ----------------
__global__ void transpose_x(const float* __restrict__ x)
{
    __shared__ float tile[32][33];
    const int b  = blockIdx.z;
    const int k0 = blockIdx.y * 32;
    const int t0 = blockIdx.x * 32;
    const int tx = threadIdx.x, ty = threadIdx.y;

    for (int kk = ty; kk < 32; kk += 8) {
        int t = t0 + tx;
        tile[kk][tx] = (t < TT) ? x[(size_t)b*DD*TT + (size_t)(k0 + kk)*TT + t] : 0.f;
    }
    __syncthreads();
    for (int tl = ty; tl < 32; tl += 8) {
        int t = t0 + tl;
        if (t < TT)
            g_xT[((size_t)t*BATCH + b)*DD + k0 + tx] = tile[tx][tl];
    }
}

__global__ void transpose_y(float* __restrict__ out)
{
    __shared__ float tile[32][33];
    const int b  = blockIdx.z;
    const int n0 = blockIdx.y * 32;
    const int t0 = blockIdx.x * 32;
    const int tx = threadIdx.x, ty = threadIdx.y;

    for (int tl = ty; tl < 32; tl += 8) {
        int t = t0 + tl;
        tile[tl][tx] = (t < TT) ? g_Y[((size_t)t*BATCH + b)*DD + n0 + tx] : 0.f;
    }
    __syncthreads();
    for (int nn = ty; nn < 32; nn += 8) {
        int t = t0 + tx;
        if (t < TT)
            out[(size_t)b*DD*TT + (size_t)(n0 + nn)*TT + t] = tile[tx][nn];
    }
}

// ---------------- launch ----------------
extern "C" void kernel_launch(void* const* d_in, const int* in_sizes, int n_in,
                              void* d_out, int out_size)
{
    (void)in_sizes; (void)n_in; (void)out_size;
    const float* x     = (const float*)d_in[0];
    const float* W_in  = (const float*)d_in[1];
    const float* b_in  = (const float*)d_in[2];
    const float* W_hid = (const float*)d_in[3];
    const float* b_hid = (const float*)d_in[4];
    const float* W2    = (const float*)d_in[5];
    const float* b2    = (const float*)d_in[6];
    const float* W3    = (const float*)d_in[7];
    const float* b3    = (const float*)d_in[8];
    const float* W_out = (const float*)d_in[9];
    const float* b_out = (const float*)d_in[10];
    const float* etas  = (const float*)d_in[11];
    float* out = (float*)d_out;

    cudaFuncSetAttribute(ernn_seq, cudaFuncAttributeMaxDynamicSharedMemorySize, SEQ_BYTES);
    cudaFuncSetAttribute(gemm64,   cudaFuncAttributeMaxDynamicSharedMemorySize, PAR_SMEM_BYTES);

    dim3 tb(32, 8);
    dim3 tgx((TT + 31)/32, DD/32, BATCH);
    transpose_x<<<tgx, tb>>>(x);

    {
        float* gWX; float* gxT;
        cudaGetSymbolAddress((void**)&gWX, g_WX);
        cudaGetSymbolAddress((void**)&gxT, g_xT);
        dim3 gg(DD/64, TB/64);
        gemm64<<<gg, 256, PAR_SMEM_BYTES>>>(gxT, W_in, b_in, gWX);
    }

    ernn_seq<<<NCTA, 256, SEQ_BYTES>>>(W_hid, b_hid, W2, b2, W3, b3, etas);

    {
        float* gH; float* gY;
        cudaGetSymbolAddress((void**)&gH, g_H);
        cudaGetSymbolAddress((void**)&gY, g_Y);
        dim3 gg(DD/64, TB/64);
        gemm64<<<gg, 256, PAR_SMEM_BYTES>>>(gH, W_out, b_out, gY);
    }

    dim3 tgy((TT + 31)/32, DD/32, BATCH);
    transpose_y<<<tgy, tb>>>(out);
}

// round 14
// speedup vs baseline: 1.1382x; 1.1382x over previous
#include <cuda_runtime.h>
#include <cstdint>

#define DD 1024
#define BATCH 64
#define TT 200
#define TB (TT*BATCH)
#define NCTA 128
#define ASTRIDE 132

typedef unsigned long long ull;

// ---------------- scratch (static __device__, no allocations) ----------------
__device__ float g_xT[TB*DD];     // x transposed: [t][b][k]
__device__ float g_WX[TB*DD];     // wx for all timesteps
__device__ float g_H [TB*DD];     // h_t for all timesteps
__device__ float g_Y [TB*DD];     // y before final transpose
__device__ float g_A0[BATCH*DD];  // h+h0  (GEMM input P1)
__device__ float g_A1[BATCH*DD];  // F1    (GEMM input P2)
__device__ float g_A2[BATCH*DD];  // T2    (GEMM input P3)
__device__ unsigned g_bar_count;
__device__ volatile unsigned g_bar_gen;

// ---------------- helpers ----------------
__device__ __forceinline__ void ffma2(ull& d, ull a, ull b) {
    asm("fma.rn.f32x2 %0, %1, %2, %0;" : "+l"(d) : "l"(a), "l"(b));
}
__device__ __forceinline__ float hsum2(ull v) {
    float lo, hi;
    asm("mov.b64 {%0,%1}, %2;" : "=f"(lo), "=f"(hi) : "l"(v));
    return lo + hi;
}
__device__ __forceinline__ float elu_f(float x) { return x > 0.f ? x : expm1f(x); }

__device__ __forceinline__ void cp16(float* dst_smem, const float* src) {
    unsigned s = (unsigned)__cvta_generic_to_shared(dst_smem);
    asm volatile("cp.async.cg.shared.global [%0], [%1], 16;" :: "r"(s), "l"(src));
}
__device__ __forceinline__ void cp_commit() {
    asm volatile("cp.async.commit_group;");
}

__device__ __forceinline__ void grid_sync() {
    __syncthreads();
    if (threadIdx.x == 0) {
        unsigned gen = g_bar_gen;
        __threadfence();
        if (atomicAdd(&g_bar_count, 1) == gridDim.x - 1) {
            g_bar_count = 0;
            __threadfence();
            g_bar_gen = gen + 1;
        } else {
            while (g_bar_gen == gen) { __nanosleep(32); }
            __threadfence();
        }
    }
    __syncthreads();
}

// ---------------- seq smem layout (floats) ----------------
#define SW_FLOATS   8192                          // per matrix: float2[kp*8+n]
#define SA_FLOATS   (64*ASTRIDE)                  // 8448 per buffer
#define RED_STRIDE  36
#define OFF_SA      (3*SW_FLOATS)                 // 24576
#define OFF_RED     (OFF_SA + 2*SA_FLOATS)        // 41472
#define OFF_H       (OFF_RED + 128*RED_STRIDE)    // 46080
#define SEQ_FLOATS  (OFF_H + 3*512)               // 47616
#define SEQ_BYTES   (SEQ_FLOATS*4)                // 190464

// ---------------- sequential-phase GEMM core ----------------
// C[64][8] = A[64][1024] @ Wslice[8][1024]^T.
// Thread tile Tm=8 (rows i*8+mg), Tn=4 (cols ng*4..+3); k-split 16 = warp(8) x kss(2).
// lane = mg + 8*ng + 16*kss. Returns dots for outputs o=tid*2 (.x) and o=tid*2+1 (.y).
__device__ __noinline__ float2 mm_phase(const float* __restrict__ Ag,
                                        const float2* __restrict__ sWm,
                                        float* __restrict__ sA,
                                        float* __restrict__ red)
{
    const int tid  = threadIdx.x;
    const int warp = tid >> 5, lane = tid & 31;
    const int mg = lane & 7, ng = (lane >> 3) & 1, kss = lane >> 4;

    ull acc[8][4];
    #pragma unroll
    for (int i = 0; i < 8; i++)
        #pragma unroll
        for (int j = 0; j < 4; j++) acc[i][j] = 0ull;

    // stage chunk 0 (cp.async; id = s*256+tid; row=id>>5, u=id&31 in 16B units)
    #pragma unroll
    for (int s = 0; s < 8; s++) {
        const int id = s*256 + tid, row = id >> 5, u = id & 31;
        cp16(sA + row*ASTRIDE + u*4, Ag + row*DD + u*4);
    }
    cp_commit();

    #pragma unroll 1
    for (int c = 0; c < 8; c++) {
        if (c < 7) {
            float* dst = sA + ((c+1) & 1) * SA_FLOATS;
            const float* src = Ag + (c+1)*128;
            #pragma unroll
            for (int s = 0; s < 8; s++) {
                const int id = s*256 + tid, row = id >> 5, u = id & 31;
                cp16(dst + row*ASTRIDE + u*4, src + row*DD + u*4);
            }
            cp_commit();
            asm volatile("cp.async.wait_group 1;");
        } else {
            asm volatile("cp.async.wait_group 0;");
        }
        __syncthreads();

        const float* sAb = sA + (c & 1) * SA_FLOATS;
        #pragma unroll
        for (int q = 0; q < 2; q++) {
            const int kc = warp*16 + kss*8 + q*4;       // chunk-local k offset
            ulonglong2 av[8];
            #pragma unroll
            for (int i = 0; i < 8; i++)
                av[i] = *(const ulonglong2*)(sAb + (i*8 + mg)*ASTRIDE + kc);

            const int kpg = (c*128 + kc) >> 1;          // global k-pair index
            const ulonglong2* wp0 = (const ulonglong2*)(sWm + (size_t)kpg*8 + ng*4);
            const ulonglong2* wp1 = (const ulonglong2*)(sWm + (size_t)(kpg+1)*8 + ng*4);
            const ulonglong2 w0a = wp0[0], w0b = wp0[1]; // k-pair kpg:   n0n1, n2n3
            const ulonglong2 w1a = wp1[0], w1b = wp1[1]; // k-pair kpg+1: n0n1, n2n3

            #pragma unroll
            for (int i = 0; i < 8; i++) {
                ffma2(acc[i][0], av[i].x, w0a.x);
                ffma2(acc[i][0], av[i].y, w1a.x);
                ffma2(acc[i][1], av[i].x, w0a.y);
                ffma2(acc[i][1], av[i].y, w1a.y);
                ffma2(acc[i][2], av[i].x, w0b.x);
                ffma2(acc[i][2], av[i].y, w1b.x);
                ffma2(acc[i][3], av[i].x, w0b.y);
                ffma2(acc[i][3], av[i].y, w1b.y);
            }
        }
        __syncthreads();
    }

    // reduce: kss partner via shfl, then 8 warps via SMEM
    float v[32];
    #pragma unroll
    for (int i = 0; i < 8; i++)
        #pragma unroll
        for (int j = 0; j < 4; j++) v[i*4+j] = hsum2(acc[i][j]);
    #pragma unroll
    for (int e = 0; e < 32; e++)
        v[e] += __shfl_xor_sync(0xffffffffu, v[e], 16);

    if (kss == 0) {
        float* r = red + (warp*16 + lane)*RED_STRIDE;
        #pragma unroll
        for (int b = 0; b < 8; b++)
            *(float4*)&r[b*4] = make_float4(v[b*4], v[b*4+1], v[b*4+2], v[b*4+3]);
    }
    __syncthreads();

    float2 out = make_float2(0.f, 0.f);
    {
        const int o0 = tid*2;
        const int m0 = o0 >> 3, n0 = o0 & 7;           // n0 even; o0+1 -> same m, n0+1
        const int lane0 = (m0 & 7) + 8*(n0 >> 2);
        const int e0    = (m0 >> 3)*4 + (n0 & 3);      // even
        #pragma unroll
        for (int w = 0; w < 8; w++) {
            float2 p = *(const float2*)&red[(w*16 + lane0)*RED_STRIDE + e0];
            out.x += p.x; out.y += p.y;
        }
    }
    __syncthreads();
    return out;
}

// ---------------- persistent sequential kernel ----------------
__global__ void __launch_bounds__(256, 1) ernn_seq(
    const float* __restrict__ Whid, const float* __restrict__ bhid,
    const float* __restrict__ Wm2,  const float* __restrict__ b2,
    const float* __restrict__ Wm3,  const float* __restrict__ b3,
    const float* __restrict__ etas)
{
    extern __shared__ float sm[];
    float2* sW1 = (float2*)(sm);
    float2* sW2 = (float2*)(sm + SW_FLOATS);
    float2* sW3 = (float2*)(sm + 2*SW_FLOATS);
    float*  sA  = sm + OFF_SA;
    float*  red = sm + OFF_RED;
    float*  sh_h  = sm + OFF_H;
    float*  sh_h0 = sh_h + 512;
    float*  sh_hp = sh_h0 + 512;

    const int tid   = threadIdx.x;
    const int nbase = blockIdx.x * 8;

    // preload W slices into interleaved float2 layout: sW[kp*8+n] = W[nbase+n][2kp..2kp+1]
    #pragma unroll 1
    for (int n = 0; n < 8; n++) {
        const float2* Wr1 = (const float2*)&Whid[(size_t)(nbase+n)*DD];
        const float2* Wr2 = (const float2*)&Wm2 [(size_t)(nbase+n)*DD];
        const float2* Wr3 = (const float2*)&Wm3 [(size_t)(nbase+n)*DD];
        for (int j = tid; j < 512; j += 256) {
            sW1[j*8 + n] = __ldg(&Wr1[j]);
            sW2[j*8 + n] = __ldg(&Wr2[j]);
            sW3[j*8 + n] = __ldg(&Wr3[j]);
        }
    }
    // zero state + own columns of g_A0
    for (int o = tid; o < 512; o += 256) {
        sh_h[o] = 0.f; sh_h0[o] = 0.f; sh_hp[o] = 0.f;
        const int m = o >> 3, n = o & 7;
        g_A0[m*DD + nbase + n] = 0.f;
    }
    grid_sync();

    // per-thread epilogue constants (thread owns outputs o0, o0+1: same m, n and n+1)
    const int o0 = tid*2;
    const int m0 = o0 >> 3, n0 = o0 & 7;
    const float bh0 = __ldg(&bhid[nbase+n0]), bh1 = __ldg(&bhid[nbase+n0+1]);
    const float b20 = __ldg(&b2[nbase+n0]),   b21 = __ldg(&b2[nbase+n0+1]);
    const float b30 = __ldg(&b3[nbase+n0]),   b31 = __ldg(&b3[nbase+n0+1]);
    float e5[5];
    #pragma unroll
    for (int k = 0; k < 5; k++) e5[k] = __ldg(&etas[k]);
    const int oidx = m0*DD + nbase + n0;   // base of this thread's float2 in [64][1024]

    #pragma unroll 1
    for (int t = 0; t < TT; t++) {
        const float* wxt = g_WX + (size_t)t * BATCH * DD;
        #pragma unroll 1
        for (int it = 0; it < 5; it++) {
            // ---- P1: F1 = elu((h+h0)@Whid^T + bhid + wx) ----
            float2 r = mm_phase(g_A0, sW1, sA, red);
            {
                const float2 wx2 = *(const float2*)&wxt[oidx];
                float2 o; o.x = elu_f(r.x + bh0 + wx2.x); o.y = elu_f(r.y + bh1 + wx2.y);
                __stcg((float2*)&g_A1[oidx], o);
            }
            grid_sync();

            // ---- P2: T2 = elu(F1@W2^T + b2) ----
            r = mm_phase(g_A1, sW2, sA, red);
            {
                float2 o; o.x = elu_f(r.x + b20); o.y = elu_f(r.y + b21);
                __stcg((float2*)&g_A2[oidx], o);
            }
            grid_sync();

            // ---- P3: Fn = elu(T2@W3^T + b3); state update ----
            r = mm_phase(g_A2, sW3, sA, red);
            {
                const float eta = e5[it];
                const float fn0 = elu_f(r.x + b30);
                const float fn1 = elu_f(r.y + b31);
                const float h0n = sh_h[o0]   + eta * (fn0 - sh_hp[o0]);
                const float h1n = sh_h[o0+1] + eta * (fn1 - sh_hp[o0+1]);
                sh_h[o0] = h0n; sh_h[o0+1] = h1n;
                float2 hp;
                if (it == 4) {
                    sh_h0[o0] = h0n; sh_h0[o0+1] = h1n;
                    hp.x = 2.f*h0n; hp.y = 2.f*h1n;
                    *(float2*)&g_H[(size_t)t*BATCH*DD + oidx] = make_float2(h0n, h1n);
                } else {
                    hp.x = h0n + sh_h0[o0]; hp.y = h1n + sh_h0[o0+1];
                }
                sh_hp[o0] = hp.x; sh_hp[o0+1] = hp.y;
                __stcg((float2*)&g_A0[oidx], hp);
            }
            grid_sync();
        }
    }
}

// ---------------- parallel tiled GEMM: C = A @ W^T + bias ----------------
#define PAR_SMEM_BYTES (2*64*ASTRIDE*4)

__global__ void __launch_bounds__(256, 2) gemm64(const float* __restrict__ A,
                                                 const float* __restrict__ Wm,
                                                 const float* __restrict__ bias,
                                                 float* __restrict__ C)
{
    extern __shared__ float smp[];
    float* sA = smp;
    float* sB = smp + 64*ASTRIDE;

    const int tid  = threadIdx.x;
    const int warp = tid >> 5, lane = tid & 31;
    const int mh = warp & 1, nq = warp >> 1;
    const int mlane = lane >> 2, nlane = lane & 3;
    const int mbase = blockIdx.y * 64, nbase = blockIdx.x * 64;

    ull acc[4][4];
    #pragma unroll
    for (int i = 0; i < 4; i++)
        #pragma unroll
        for (int j = 0; j < 4; j++) acc[i][j] = 0ull;

    #pragma unroll 1
    for (int c = 0; c < 8; c++) {
        if (c) __syncthreads();
        #pragma unroll
        for (int p = 0; p < 8; p++) {
            const int row = p*8 + warp;
            *(ulonglong2*)&sA[row*ASTRIDE + lane*4] =
                __ldg((const ulonglong2*)(A  + (size_t)(mbase+row)*DD + c*128 + lane*4));
            *(ulonglong2*)&sB[row*ASTRIDE + lane*4] =
                __ldg((const ulonglong2*)(Wm + (size_t)(nbase+row)*DD + c*128 + lane*4));
        }
        __syncthreads();
        #pragma unroll 4
        for (int q = 0; q < 32; q++) {
            const int k0 = q*4;
            ulonglong2 a[4], w[4];
            #pragma unroll
            for (int i = 0; i < 4; i++)
                a[i] = *(const ulonglong2*)&sA[(mh*32 + i*8 + mlane)*ASTRIDE + k0];
            #pragma unroll
            for (int j = 0; j < 4; j++)
                w[j] = *(const ulonglong2*)&sB[(nq*16 + j*4 + nlane)*ASTRIDE + k0];
            #pragma unroll
            for (int i = 0; i < 4; i++)
                #pragma unroll
                for (int j = 0; j < 4; j++) {
                    ffma2(acc[i][j], a[i].x, w[j].x);
                    ffma2(acc[i][j], a[i].y, w[j].y);
                }
        }
    }
    #pragma unroll
    for (int i = 0; i < 4; i++)
        #pragma unroll
        for (int j = 0; j < 4; j++) {
            const int m = mbase + mh*32 + i*8 + mlane;
            const int n = nbase + nq*16 + j*4 + nlane;
            C[(size_t)m*DD + n] = hsum2(acc[i][j]) + __ldg(&bias[n]);
        }
}

// ---------------- transposes ----------------
__global__ void transpose_x(const float* __restrict__ x)
{
    __shared__ float tile[32][33];
    const int b  = blockIdx.z;
    const int k0 = blockIdx.y * 32;
    const int t0 = blockIdx.x * 32;
    const int tx = threadIdx.x, ty = threadIdx.y;

    for (int kk = ty; kk < 32; kk += 8) {
        int t = t0 + tx;
        tile[kk][tx] = (t < TT) ? x[(size_t)b*DD*TT + (size_t)(k0 + kk)*TT + t] : 0.f;
    }
    __syncthreads();
    for (int tl = ty; tl < 32; tl += 8) {
        int t = t0 + tl;
        if (t < TT)
            g_xT[((size_t)t*BATCH + b)*DD + k0 + tx] = tile[tx][tl];
    }
}

__global__ void transpose_y(float* __restrict__ out)
{
    __shared__ float tile[32][33];
    const int b  = blockIdx.z;
    const int n0 = blockIdx.y * 32;
    const int t0 = blockIdx.x * 32;
    const int tx = threadIdx.x, ty = threadIdx.y;

    for (int tl = ty; tl < 32; tl += 8) {
        int t = t0 + tl;
        tile[tl][tx] = (t < TT) ? g_Y[((size_t)t*BATCH + b)*DD + n0 + tx] : 0.f;
    }
    __syncthreads();
    for (int nn = ty; nn < 32; nn += 8) {
        int t = t0 + tx;
        if (t < TT)
            out[(size_t)b*DD*TT + (size_t)(n0 + nn)*TT + t] = tile[tx][nn];
    }
}

// ---------------- launch ----------------
extern "C" void kernel_launch(void* const* d_in, const int* in_sizes, int n_in,
                              void* d_out, int out_size)
{
    (void)in_sizes; (void)n_in; (void)out_size;
    const float* x     = (const float*)d_in[0];
    const float* W_in  = (const float*)d_in[1];
    const float* b_in  = (const float*)d_in[2];
    const float* W_hid = (const float*)d_in[3];
    const float* b_hid = (const float*)d_in[4];
    const float* W2    = (const float*)d_in[5];
    const float* b2    = (const float*)d_in[6];
    const float* W3    = (const float*)d_in[7];
    const float* b3    = (const float*)d_in[8];
    const float* W_out = (const float*)d_in[9];
    const float* b_out = (const float*)d_in[10];
    const float* etas  = (const float*)d_in[11];
    float* out = (float*)d_out;

    cudaFuncSetAttribute(ernn_seq, cudaFuncAttributeMaxDynamicSharedMemorySize, SEQ_BYTES);
    cudaFuncSetAttribute(gemm64,   cudaFuncAttributeMaxDynamicSharedMemorySize, PAR_SMEM_BYTES);

    dim3 tb(32, 8);
    dim3 tgx((TT + 31)/32, DD/32, BATCH);
    transpose_x<<<tgx, tb>>>(x);

    {
        float* gWX; float* gxT;
        cudaGetSymbolAddress((void**)&gWX, g_WX);
        cudaGetSymbolAddress((void**)&gxT, g_xT);
        dim3 gg(DD/64, TB/64);
        gemm64<<<gg, 256, PAR_SMEM_BYTES>>>(gxT, W_in, b_in, gWX);
    }

    ernn_seq<<<NCTA, 256, SEQ_BYTES>>>(W_hid, b_hid, W2, b2, W3, b3, etas);

    {
        float* gH; float* gY;
        cudaGetSymbolAddress((void**)&gH, g_H);
        cudaGetSymbolAddress((void**)&gY, g_Y);
        dim3 gg(DD/64, TB/64);
        gemm64<<<gg, 256, PAR_SMEM_BYTES>>>(gH, W_out, b_out, gY);
    }

    dim3 tgy((TT + 31)/32, DD/32, BATCH);
    transpose_y<<<tgy, tb>>>(out);
}

// round 15
// speedup vs baseline: 1.1758x; 1.0330x over previous
#include <cuda_runtime.h>
#include <cstdint>

#define DD 1024
#define BATCH 64
#define TT 200
#define TB (TT*BATCH)
#define NCTA 128
#define ASTRIDE 132

typedef unsigned long long ull;

// ---------------- scratch (static __device__, no allocations) ----------------
__device__ float g_xT[TB*DD];     // x transposed: [t][b][k]
__device__ float g_WX[TB*DD];     // wx for all timesteps
__device__ float g_H [TB*DD];     // h_t for all timesteps
__device__ float g_Y [TB*DD];     // y before final transpose
__device__ float g_A0[BATCH*DD];  // h+h0  (GEMM input P1)
__device__ float g_A1[BATCH*DD];  // F1    (GEMM input P2)
__device__ float g_A2[BATCH*DD];  // T2    (GEMM input P3)
__device__ unsigned g_flags[NCTA*32];   // per-CTA barrier flags, 128B apart

// ---------------- helpers ----------------
__device__ __forceinline__ void ffma2(ull& d, ull a, ull b) {
    asm("fma.rn.f32x2 %0, %1, %2, %0;" : "+l"(d) : "l"(a), "l"(b));
}
__device__ __forceinline__ float hsum2(ull v) {
    float lo, hi;
    asm("mov.b64 {%0,%1}, %2;" : "=f"(lo), "=f"(hi) : "l"(v));
    return lo + hi;
}
__device__ __forceinline__ float elu_f(float x) { return x > 0.f ? x : expm1f(x); }

__device__ __forceinline__ void cp16(float* dst_smem, const float* src) {
    unsigned s = (unsigned)__cvta_generic_to_shared(dst_smem);
    asm volatile("cp.async.cg.shared.global [%0], [%1], 16;" :: "r"(s), "l"(src));
}
__device__ __forceinline__ void cp_commit() {
    asm volatile("cp.async.commit_group;");
}

// Flag-array grid barrier: CTA b release-stores phase to g_flags[b*32];
// lanes 0..127 each acquire-poll one CTA's flag. No atomic contention.
__device__ __forceinline__ void grid_bar(unsigned phase) {
    __syncthreads();
    const int tid = threadIdx.x;
    if (tid == 0) {
        unsigned* p = &g_flags[blockIdx.x * 32];
        asm volatile("st.release.gpu.global.u32 [%0], %1;" :: "l"(p), "r"(phase) : "memory");
    }
    if (tid < NCTA) {
        const unsigned* p = &g_flags[tid * 32];
        unsigned v;
        do {
            asm volatile("ld.acquire.gpu.global.u32 %0, [%1];" : "=r"(v) : "l"(p) : "memory");
        } while ((int)(v - phase) < 0);
    }
    __syncthreads();
}

// ---------------- seq smem layout (floats) ----------------
#define SW_FLOATS   8192                          // per matrix: float2[kp*8+n]
#define SA_FLOATS   (64*ASTRIDE)                  // 8448 per buffer
#define RED_STRIDE  36
#define OFF_SA      (3*SW_FLOATS)                 // 24576
#define OFF_RED     (OFF_SA + 2*SA_FLOATS)        // 41472
#define OFF_H       (OFF_RED + 128*RED_STRIDE)    // 46080
#define SEQ_FLOATS  (OFF_H + 3*512)               // 47616
#define SEQ_BYTES   (SEQ_FLOATS*4)                // 190464

// ---------------- sequential-phase GEMM core ----------------
// C[64][8] = A[64][1024] @ Wslice[8][1024]^T.
// Thread tile Tm=8 (rows i*8+mg), Tn=4 (cols ng*4..+3); k-split 16 = warp(8) x kss(2).
// lane = mg + 8*ng + 16*kss. Returns dots for outputs o=tid*2 (.x) and o=tid*2+1 (.y).
__device__ __noinline__ float2 mm_phase(const float* __restrict__ Ag,
                                        const float2* __restrict__ sWm,
                                        float* __restrict__ sA,
                                        float* __restrict__ red)
{
    const int tid  = threadIdx.x;
    const int warp = tid >> 5, lane = tid & 31;
    const int mg = lane & 7, ng = (lane >> 3) & 1, kss = lane >> 4;

    ull acc[8][4];
    #pragma unroll
    for (int i = 0; i < 8; i++)
        #pragma unroll
        for (int j = 0; j < 4; j++) acc[i][j] = 0ull;

    // stage chunk 0 (cp.async; id = s*256+tid; row=id>>5, u=id&31 in 16B units)
    #pragma unroll
    for (int s = 0; s < 8; s++) {
        const int id = s*256 + tid, row = id >> 5, u = id & 31;
        cp16(sA + row*ASTRIDE + u*4, Ag + row*DD + u*4);
    }
    cp_commit();

    #pragma unroll 1
    for (int c = 0; c < 8; c++) {
        if (c < 7) {
            float* dst = sA + ((c+1) & 1) * SA_FLOATS;
            const float* src = Ag + (c+1)*128;
            #pragma unroll
            for (int s = 0; s < 8; s++) {
                const int id = s*256 + tid, row = id >> 5, u = id & 31;
                cp16(dst + row*ASTRIDE + u*4, src + row*DD + u*4);
            }
            cp_commit();
            asm volatile("cp.async.wait_group 1;");
        } else {
            asm volatile("cp.async.wait_group 0;");
        }
        __syncthreads();

        const float* sAb = sA + (c & 1) * SA_FLOATS;
        #pragma unroll
        for (int q = 0; q < 2; q++) {
            const int kc = warp*16 + kss*8 + q*4;       // chunk-local k offset
            ulonglong2 av[8];
            #pragma unroll
            for (int i = 0; i < 8; i++)
                av[i] = *(const ulonglong2*)(sAb + (i*8 + mg)*ASTRIDE + kc);

            const int kpg = (c*128 + kc) >> 1;          // global k-pair index
            const ulonglong2* wp0 = (const ulonglong2*)(sWm + (size_t)kpg*8 + ng*4);
            const ulonglong2* wp1 = (const ulonglong2*)(sWm + (size_t)(kpg+1)*8 + ng*4);
            const ulonglong2 w0a = wp0[0], w0b = wp0[1]; // k-pair kpg:   n0n1, n2n3
            const ulonglong2 w1a = wp1[0], w1b = wp1[1]; // k-pair kpg+1: n0n1, n2n3

            #pragma unroll
            for (int i = 0; i < 8; i++) {
                ffma2(acc[i][0], av[i].x, w0a.x);
                ffma2(acc[i][0], av[i].y, w1a.x);
                ffma2(acc[i][1], av[i].x, w0a.y);
                ffma2(acc[i][1], av[i].y, w1a.y);
                ffma2(acc[i][2], av[i].x, w0b.x);
                ffma2(acc[i][2], av[i].y, w1b.x);
                ffma2(acc[i][3], av[i].x, w0b.y);
                ffma2(acc[i][3], av[i].y, w1b.y);
            }
        }
        __syncthreads();
    }

    // reduce: kss partner via shfl, then 8 warps via SMEM
    float v[32];
    #pragma unroll
    for (int i = 0; i < 8; i++)
        #pragma unroll
        for (int j = 0; j < 4; j++) v[i*4+j] = hsum2(acc[i][j]);
    #pragma unroll
    for (int e = 0; e < 32; e++)
        v[e] += __shfl_xor_sync(0xffffffffu, v[e], 16);

    if (kss == 0) {
        float* r = red + (warp*16 + lane)*RED_STRIDE;
        #pragma unroll
        for (int b = 0; b < 8; b++)
            *(float4*)&r[b*4] = make_float4(v[b*4], v[b*4+1], v[b*4+2], v[b*4+3]);
    }
    __syncthreads();

    float2 out = make_float2(0.f, 0.f);
    {
        const int o0 = tid*2;
        const int m0 = o0 >> 3, n0 = o0 & 7;           // n0 even; o0+1 -> same m, n0+1
        const int lane0 = (m0 & 7) + 8*(n0 >> 2);
        const int e0    = (m0 >> 3)*4 + (n0 & 3);      // even
        #pragma unroll
        for (int w = 0; w < 8; w++) {
            float2 p = *(const float2*)&red[(w*16 + lane0)*RED_STRIDE + e0];
            out.x += p.x; out.y += p.y;
        }
    }
    __syncthreads();
    return out;
}

// ---------------- persistent sequential kernel ----------------
__global__ void __launch_bounds__(256, 1) ernn_seq(
    const float* __restrict__ Whid, const float* __restrict__ bhid,
    const float* __restrict__ Wm2,  const float* __restrict__ b2,
    const float* __restrict__ Wm3,  const float* __restrict__ b3,
    const float* __restrict__ etas)
{
    extern __shared__ float sm[];
    float2* sW1 = (float2*)(sm);
    float2* sW2 = (float2*)(sm + SW_FLOATS);
    float2* sW3 = (float2*)(sm + 2*SW_FLOATS);
    float*  sA  = sm + OFF_SA;
    float*  red = sm + OFF_RED;
    float*  sh_h  = sm + OFF_H;
    float*  sh_h0 = sh_h + 512;
    float*  sh_hp = sh_h0 + 512;

    const int tid   = threadIdx.x;
    const int nbase = blockIdx.x * 8;

    // barrier phase base: flags are uniform at launch (0 first time, final value after)
    unsigned bar_ph;
    {
        const unsigned* p = &g_flags[blockIdx.x * 32];
        asm volatile("ld.global.u32 %0, [%1];" : "=r"(bar_ph) : "l"(p));
    }

    // preload W slices into interleaved float2 layout: sW[kp*8+n] = W[nbase+n][2kp..2kp+1]
    #pragma unroll 1
    for (int n = 0; n < 8; n++) {
        const float2* Wr1 = (const float2*)&Whid[(size_t)(nbase+n)*DD];
        const float2* Wr2 = (const float2*)&Wm2 [(size_t)(nbase+n)*DD];
        const float2* Wr3 = (const float2*)&Wm3 [(size_t)(nbase+n)*DD];
        for (int j = tid; j < 512; j += 256) {
            sW1[j*8 + n] = __ldg(&Wr1[j]);
            sW2[j*8 + n] = __ldg(&Wr2[j]);
            sW3[j*8 + n] = __ldg(&Wr3[j]);
        }
    }
    // zero state + own columns of g_A0
    for (int o = tid; o < 512; o += 256) {
        sh_h[o] = 0.f; sh_h0[o] = 0.f; sh_hp[o] = 0.f;
        const int m = o >> 3, n = o & 7;
        g_A0[m*DD + nbase + n] = 0.f;
    }
    bar_ph++; grid_bar(bar_ph);

    // per-thread epilogue constants (thread owns outputs o0, o0+1: same m, n and n+1)
    const int o0 = tid*2;
    const int m0 = o0 >> 3, n0 = o0 & 7;
    const float bh0 = __ldg(&bhid[nbase+n0]), bh1 = __ldg(&bhid[nbase+n0+1]);
    const float b20 = __ldg(&b2[nbase+n0]),   b21 = __ldg(&b2[nbase+n0+1]);
    const float b30 = __ldg(&b3[nbase+n0]),   b31 = __ldg(&b3[nbase+n0+1]);
    float e5[5];
    #pragma unroll
    for (int k = 0; k < 5; k++) e5[k] = __ldg(&etas[k]);
    const int oidx = m0*DD + nbase + n0;   // base of this thread's float2 in [64][1024]

    #pragma unroll 1
    for (int t = 0; t < TT; t++) {
        const float* wxt = g_WX + (size_t)t * BATCH * DD;
        #pragma unroll 1
        for (int it = 0; it < 5; it++) {
            // ---- P1: F1 = elu((h+h0)@Whid^T + bhid + wx) ----
            float2 r = mm_phase(g_A0, sW1, sA, red);
            {
                const float2 wx2 = *(const float2*)&wxt[oidx];
                float2 o; o.x = elu_f(r.x + bh0 + wx2.x); o.y = elu_f(r.y + bh1 + wx2.y);
                __stcg((float2*)&g_A1[oidx], o);
            }
            bar_ph++; grid_bar(bar_ph);

            // ---- P2: T2 = elu(F1@W2^T + b2) ----
            r = mm_phase(g_A1, sW2, sA, red);
            {
                float2 o; o.x = elu_f(r.x + b20); o.y = elu_f(r.y + b21);
                __stcg((float2*)&g_A2[oidx], o);
            }
            bar_ph++; grid_bar(bar_ph);

            // ---- P3: Fn = elu(T2@W3^T + b3); state update ----
            r = mm_phase(g_A2, sW3, sA, red);
            {
                const float eta = e5[it];
                const float fn0 = elu_f(r.x + b30);
                const float fn1 = elu_f(r.y + b31);
                const float h0n = sh_h[o0]   + eta * (fn0 - sh_hp[o0]);
                const float h1n = sh_h[o0+1] + eta * (fn1 - sh_hp[o0+1]);
                sh_h[o0] = h0n; sh_h[o0+1] = h1n;
                float2 hp;
                if (it == 4) {
                    sh_h0[o0] = h0n; sh_h0[o0+1] = h1n;
                    hp.x = 2.f*h0n; hp.y = 2.f*h1n;
                    *(float2*)&g_H[(size_t)t*BATCH*DD + oidx] = make_float2(h0n, h1n);
                } else {
                    hp.x = h0n + sh_h0[o0]; hp.y = h1n + sh_h0[o0+1];
                }
                sh_hp[o0] = hp.x; sh_hp[o0+1] = hp.y;
                __stcg((float2*)&g_A0[oidx], hp);
            }
            bar_ph++; grid_bar(bar_ph);
        }
    }
}

// ---------------- parallel tiled GEMM: C = A @ W^T + bias ----------------
#define PAR_SMEM_BYTES (2*64*ASTRIDE*4)

__global__ void __launch_bounds__(256, 2) gemm64(const float* __restrict__ A,
                                                 const float* __restrict__ Wm,
                                                 const float* __restrict__ bias,
                                                 float* __restrict__ C)
{
    extern __shared__ float smp[];
    float* sA = smp;
    float* sB = smp + 64*ASTRIDE;

    const int tid  = threadIdx.x;
    const int warp = tid >> 5, lane = tid & 31;
    const int mh = warp & 1, nq = warp >> 1;
    const int mlane = lane >> 2, nlane = lane & 3;
    const int mbase = blockIdx.y * 64, nbase = blockIdx.x * 64;

    ull acc[4][4];
    #pragma unroll
    for (int i = 0; i < 4; i++)
        #pragma unroll
        for (int j = 0; j < 4; j++) acc[i][j] = 0ull;

    #pragma unroll 1
    for (int c = 0; c < 8; c++) {
        if (c) __syncthreads();
        #pragma unroll
        for (int p = 0; p < 8; p++) {
            const int row = p*8 + warp;
            *(ulonglong2*)&sA[row*ASTRIDE + lane*4] =
                __ldg((const ulonglong2*)(A  + (size_t)(mbase+row)*DD + c*128 + lane*4));
            *(ulonglong2*)&sB[row*ASTRIDE + lane*4] =
                __ldg((const ulonglong2*)(Wm + (size_t)(nbase+row)*DD + c*128 + lane*4));
        }
        __syncthreads();
        #pragma unroll 4
        for (int q = 0; q < 32; q++) {
            const int k0 = q*4;
            ulonglong2 a[4], w[4];
            #pragma unroll
            for (int i = 0; i < 4; i++)
                a[i] = *(const ulonglong2*)&sA[(mh*32 + i*8 + mlane)*ASTRIDE + k0];
            #pragma unroll
            for (int j = 0; j < 4; j++)
                w[j] = *(const ulonglong2*)&sB[(nq*16 + j*4 + nlane)*ASTRIDE + k0];
            #pragma unroll
            for (int i = 0; i < 4; i++)
                #pragma unroll
                for (int j = 0; j < 4; j++) {
                    ffma2(acc[i][j], a[i].x, w[j].x);
                    ffma2(acc[i][j], a[i].y, w[j].y);
                }
        }
    }
    #pragma unroll
    for (int i = 0; i < 4; i++)
        #pragma unroll
        for (int j = 0; j < 4; j++) {
            const int m = mbase + mh*32 + i*8 + mlane;
            const int n = nbase + nq*16 + j*4 + nlane;
            C[(size_t)m*DD + n] = hsum2(acc[i][j]) + __ldg(&bias[n]);
        }
}

// ---------------- transposes ----------------
__global__ void transpose_x(const float* __restrict__ x)
{
    __shared__ float tile[32][33];
    const int b  = blockIdx.z;
    const int k0 = blockIdx.y * 32;
    const int t0 = blockIdx.x * 32;
    const int tx = threadIdx.x, ty = threadIdx.y;

    for (int kk = ty; kk < 32; kk += 8) {
        int t = t0 + tx;
        tile[kk][tx] = (t < TT) ? x[(size_t)b*DD*TT + (size_t)(k0 + kk)*TT + t] : 0.f;
    }
    __syncthreads();
    for (int tl = ty; tl < 32; tl += 8) {
        int t = t0 + tl;
        if (t < TT)
            g_xT[((size_t)t*BATCH + b)*DD + k0 + tx] = tile[tx][tl];
    }
}

__global__ void transpose_y(float* __restrict__ out)
{
    __shared__ float tile[32][33];
    const int b  = blockIdx.z;
    const int n0 = blockIdx.y * 32;
    const int t0 = blockIdx.x * 32;
    const int tx = threadIdx.x, ty = threadIdx.y;

    for (int tl = ty; tl < 32; tl += 8) {
        int t = t0 + tl;
        tile[tl][tx] = (t < TT) ? g_Y[((size_t)t*BATCH + b)*DD + n0 + tx] : 0.f;
    }
    __syncthreads();
    for (int nn = ty; nn < 32; nn += 8) {
        int t = t0 + tx;
        if (t < TT)
            out[(size_t)b*DD*TT + (size_t)(n0 + nn)*TT + t] = tile[tx][nn];
    }
}

// ---------------- launch ----------------
extern "C" void kernel_launch(void* const* d_in, const int* in_sizes, int n_in,
                              void* d_out, int out_size)
{
    (void)in_sizes; (void)n_in; (void)out_size;
    const float* x     = (const float*)d_in[0];
    const float* W_in  = (const float*)d_in[1];
    const float* b_in  = (const float*)d_in[2];
    const float* W_hid = (const float*)d_in[3];
    const float* b_hid = (const float*)d_in[4];
    const float* W2    = (const float*)d_in[5];
    const float* b2    = (const float*)d_in[6];
    const float* W3    = (const float*)d_in[7];
    const float* b3    = (const float*)d_in[8];
    const float* W_out = (const float*)d_in[9];
    const float* b_out = (const float*)d_in[10];
    const float* etas  = (const float*)d_in[11];
    float* out = (float*)d_out;

    cudaFuncSetAttribute(ernn_seq, cudaFuncAttributeMaxDynamicSharedMemorySize, SEQ_BYTES);
    cudaFuncSetAttribute(gemm64,   cudaFuncAttributeMaxDynamicSharedMemorySize, PAR_SMEM_BYTES);

    dim3 tb(32, 8);
    dim3 tgx((TT + 31)/32, DD/32, BATCH);
    transpose_x<<<tgx, tb>>>(x);

    {
        float* gWX; float* gxT;
        cudaGetSymbolAddress((void**)&gWX, g_WX);
        cudaGetSymbolAddress((void**)&gxT, g_xT);
        dim3 gg(DD/64, TB/64);
        gemm64<<<gg, 256, PAR_SMEM_BYTES>>>(gxT, W_in, b_in, gWX);
    }

    ernn_seq<<<NCTA, 256, SEQ_BYTES>>>(W_hid, b_hid, W2, b2, W3, b3, etas);

    {
        float* gH; float* gY;
        cudaGetSymbolAddress((void**)&gH, g_H);
        cudaGetSymbolAddress((void**)&gY, g_Y);
        dim3 gg(DD/64, TB/64);
        gemm64<<<gg, 256, PAR_SMEM_BYTES>>>(gH, W_out, b_out, gY);
    }

    dim3 tgy((TT + 31)/32, DD/32, BATCH);
    transpose_y<<<tgy, tb>>>(out);
}

// round 16
// speedup vs baseline: 1.2739x; 1.0834x over previous
#include <cuda_runtime.h>
#include <cstdint>

#define DD 1024
#define BATCH 64
#define TT 200
#define TB (TT*BATCH)
#define NCTA 128

typedef unsigned long long ull;

// ---------------- scratch (static __device__, no allocations) ----------------
__device__ float g_xT[TB*DD];      // x transposed: [t][b][k]
__device__ float g_WX[TB*DD];      // wx for all timesteps
__device__ float g_H [TB*DD];      // h_t for all timesteps
__device__ float g_Y [TB*DD];      // y before final transpose
__device__ float g_A0[BATCH*DD];   // h+h0  (GEMM input P1)
__device__ float g_A1[BATCH*DD];   // F1    (GEMM input P2)
__device__ float g_A2[BATCH*DD];   // T2    (GEMM input P3)
__device__ float g_part[NCTA*2048];     // per-CTA partial C [64][32]
__device__ unsigned g_pflag[NCTA*32];   // partial-ready flags (128B apart)
__device__ unsigned g_aflag[NCTA*32];   // activation-ready flags

// ---------------- helpers ----------------
__device__ __forceinline__ void ffma2(ull& d, ull a, ull b) {
    asm("fma.rn.f32x2 %0, %1, %2, %0;" : "+l"(d) : "l"(a), "l"(b));
}
__device__ __forceinline__ float hsum2(ull v) {
    float lo, hi;
    asm("mov.b64 {%0,%1}, %2;" : "=f"(lo), "=f"(hi) : "l"(v));
    return lo + hi;
}
__device__ __forceinline__ float elu_f(float x) { return x > 0.f ? x : expm1f(x); }

__device__ __forceinline__ void cp16(float* dst_smem, const float* src) {
    unsigned s = (unsigned)__cvta_generic_to_shared(dst_smem);
    asm volatile("cp.async.cg.shared.global [%0], [%1], 16;" :: "r"(s), "l"(src));
}
__device__ __forceinline__ void cp_commit() {
    asm volatile("cp.async.commit_group;");
}
__device__ __forceinline__ void rel_store(unsigned* p, unsigned v) {
    asm volatile("st.release.gpu.global.u32 [%0], %1;" :: "l"(p), "r"(v) : "memory");
}
__device__ __forceinline__ void acq_poll(const unsigned* p, unsigned target) {
    unsigned v;
    do {
        asm volatile("ld.acquire.gpu.global.u32 %0, [%1];" : "=r"(v) : "l"(p) : "memory");
    } while ((int)(v - target) < 0);
}

// ---------------- seq smem layout (floats) ----------------
// sW: 3 matrices x [128 kpairs][34 pad] float2  = 3*4352 float2 = 26112 floats
// sA: 2 x [64 rows][68]                         = 8704 floats
// red: [64][36]                                 = 2304 floats
// state: 3 x 512
#define SWF2     4352
#define OFF_SA   26112
#define SAF      4352
#define OFF_RED  (OFF_SA + 2*SAF)       // 34816
#define OFF_H    (OFF_RED + 2304)       // 37120
#define SEQ_FLOATS (OFF_H + 3*512)      // 38656
#define SEQ_BYTES  (SEQ_FLOATS*4)       // 154624

// ---------------- per-CTA partial GEMM ----------------
// partial[64][32] = A[64][kbase..kbase+255] @ Wslice[32][256]^T
// warps: wq = warp&3 (8-col quad), wh = warp>>2 (k half of chunk)
// lane: mg = lane&7 (m sub), ng = (lane>>3)&1 (4-col half), kss = lane>>4 (k quarter)
// Result: lanes with kss==0 in warps wh==0 hold v[i*4+j] = full-k-slice dot for
// row i*8+mg, col wq*8+ng*4+j; they also store the partial to g_part.
__device__ __forceinline__ void mm_partial(const float* __restrict__ Ag, int kbase,
                                           const float2* __restrict__ sWm,
                                           float* __restrict__ sA,
                                           float* __restrict__ red,
                                           int bid)
{
    const int tid  = threadIdx.x;
    const int warp = tid >> 5, lane = tid & 31;
    const int wq = warp & 3, wh = warp >> 2;
    const int mg = lane & 7, ng = (lane >> 3) & 1, kss = lane >> 4;
    const int n0 = wq*8 + ng*4;

    ull acc[8][4];
    #pragma unroll
    for (int i = 0; i < 8; i++)
        #pragma unroll
        for (int j = 0; j < 4; j++) acc[i][j] = 0ull;

    // stage chunk 0: 64 rows x 64 floats (16KB); 4 cp16/thread
    {
        const float* src = Ag + kbase;
        #pragma unroll
        for (int r2 = 0; r2 < 4; r2++) {
            const int id = r2*256 + tid, row = id >> 4, u = id & 15;
            cp16(sA + row*68 + u*4, src + row*DD + u*4);
        }
        cp_commit();
    }

    #pragma unroll 1
    for (int c = 0; c < 4; c++) {
        if (c < 3) {
            float* dst = sA + ((c+1) & 1) * SAF;
            const float* src = Ag + kbase + (c+1)*64;
            #pragma unroll
            for (int r2 = 0; r2 < 4; r2++) {
                const int id = r2*256 + tid, row = id >> 4, u = id & 15;
                cp16(dst + row*68 + u*4, src + row*DD + u*4);
            }
            cp_commit();
            asm volatile("cp.async.wait_group 1;");
        } else {
            asm volatile("cp.async.wait_group 0;");
        }
        __syncthreads();

        const float* sAb = sA + (c & 1) * SAF;
        #pragma unroll
        for (int q = 0; q < 4; q++) {
            const int kc  = wh*32 + kss*16 + q*4;     // chunk-local k
            const int kpl = c*32 + (kc >> 1);         // slice-local k-pair
            const ulonglong2 wa0 = *(const ulonglong2*)(sWm + (size_t)kpl*34 + n0);
            const ulonglong2 wa1 = *(const ulonglong2*)(sWm + (size_t)kpl*34 + n0 + 2);
            const ulonglong2 wb0 = *(const ulonglong2*)(sWm + (size_t)(kpl+1)*34 + n0);
            const ulonglong2 wb1 = *(const ulonglong2*)(sWm + (size_t)(kpl+1)*34 + n0 + 2);

            ulonglong2 av[8];
            #pragma unroll
            for (int i = 0; i < 8; i++)
                av[i] = *(const ulonglong2*)(sAb + (i*8 + mg)*68 + kc);

            #pragma unroll
            for (int i = 0; i < 8; i++) {
                ffma2(acc[i][0], av[i].x, wa0.x);
                ffma2(acc[i][0], av[i].y, wb0.x);
                ffma2(acc[i][1], av[i].x, wa0.y);
                ffma2(acc[i][1], av[i].y, wb0.y);
                ffma2(acc[i][2], av[i].x, wa1.x);
                ffma2(acc[i][2], av[i].y, wb1.x);
                ffma2(acc[i][3], av[i].x, wa1.y);
                ffma2(acc[i][3], av[i].y, wb1.y);
            }
        }
        __syncthreads();
    }

    // reduce over kss (shfl) and wh (smem)
    float v[32];
    #pragma unroll
    for (int i = 0; i < 8; i++)
        #pragma unroll
        for (int j = 0; j < 4; j++) v[i*4+j] = hsum2(acc[i][j]);
    #pragma unroll
    for (int e = 0; e < 32; e++)
        v[e] += __shfl_xor_sync(0xffffffffu, v[e], 16);

    if (wh == 1 && lane < 16) {
        float* r = red + (wq*16 + lane)*36;
        #pragma unroll
        for (int b = 0; b < 8; b++)
            *(float4*)&r[b*4] = make_float4(v[b*4], v[b*4+1], v[b*4+2], v[b*4+3]);
    }
    __syncthreads();
    if (wh == 0 && lane < 16) {
        const float* r = red + (wq*16 + lane)*36;
        #pragma unroll
        for (int b = 0; b < 8; b++) {
            float4 p = *(const float4*)&r[b*4];
            v[b*4] += p.x; v[b*4+1] += p.y; v[b*4+2] += p.z; v[b*4+3] += p.w;
        }
        // store partial [row][col] for this CTA
        float* pb = g_part + (size_t)bid*2048;
        #pragma unroll
        for (int i = 0; i < 8; i++) {
            float4 o = make_float4(v[i*4], v[i*4+1], v[i*4+2], v[i*4+3]);
            __stcg((float4*)&pb[(i*8 + mg)*32 + n0], o);
        }
    }
    __syncthreads();
}

// ---------------- persistent sequential kernel ----------------
__global__ void __launch_bounds__(256, 1) ernn_seq(
    const float* __restrict__ Whid, const float* __restrict__ bhid,
    const float* __restrict__ Wm2,  const float* __restrict__ b2,
    const float* __restrict__ Wm3,  const float* __restrict__ b3,
    const float* __restrict__ etas)
{
    extern __shared__ float sm[];
    float2* sW1 = (float2*)sm;
    float2* sW2 = sW1 + SWF2;
    float2* sW3 = sW2 + SWF2;
    float*  sA  = sm + OFF_SA;
    float*  red = sm + OFF_RED;
    float*  sh_h  = sm + OFF_H;
    float*  sh_h0 = sh_h + 512;
    float*  sh_hp = sh_h0 + 512;

    const int tid = threadIdx.x;
    const int bid = blockIdx.x;
    const int g = bid >> 2, s = bid & 3;
    const int nbg = g * 32;          // this group's first col
    const int kbase = s * 256;       // this CTA's K slice

    // flag bases (flags are uniform across CTAs at every launch)
    unsigned pbase, abase;
    asm volatile("ld.global.u32 %0, [%1];" : "=r"(pbase) : "l"(&g_pflag[bid*32]));
    asm volatile("ld.global.u32 %0, [%1];" : "=r"(abase) : "l"(&g_aflag[bid*32]));

    // load weight slices: sW[kp*34+n] = {W[nbg+n][kbase+2kp], W[nbg+n][kbase+2kp+1]}
    for (int idx = tid; idx < 128*32; idx += 256) {
        const int kp = idx >> 5, n = idx & 31;
        sW1[kp*34 + n] = __ldg((const float2*)&Whid[(size_t)(nbg+n)*DD + kbase + 2*kp]);
        sW2[kp*34 + n] = __ldg((const float2*)&Wm2 [(size_t)(nbg+n)*DD + kbase + 2*kp]);
        sW3[kp*34 + n] = __ldg((const float2*)&Wm3 [(size_t)(nbg+n)*DD + kbase + 2*kp]);
    }

    // combine-stage coordinates: stripe rows s*16..+15, cols nbg..+31
    const int cm = tid >> 4;               // 0..15 stripe-local row
    const int cc = (tid & 15) * 2;         // 0..30 local col (float2)
    const int gm = s*16 + cm;              // global batch row
    const int aidx = gm*DD + nbg + cc;     // activation float2 base
    const int o0 = tid * 2;                // state index (cm*32+cc == tid*2)

    // init state + A0 stripe
    sh_h[o0] = 0.f; sh_h[o0+1] = 0.f;
    sh_h0[o0] = 0.f; sh_h0[o0+1] = 0.f;
    sh_hp[o0] = 0.f; sh_hp[o0+1] = 0.f;
    __stcg((float2*)&g_A0[aidx], make_float2(0.f, 0.f));
    __syncthreads();
    if (tid == 0) rel_store(&g_aflag[bid*32], abase + 1);
    if (tid < NCTA) acq_poll(&g_aflag[tid*32], abase + 1);
    __syncthreads();

    // combine constants
    const float2 bh = __ldg((const float2*)&bhid[nbg + cc]);
    const float2 bb2 = __ldg((const float2*)&b2[nbg + cc]);
    const float2 bb3 = __ldg((const float2*)&b3[nbg + cc]);
    float e5[5];
    #pragma unroll
    for (int k = 0; k < 5; k++) e5[k] = __ldg(&etas[k]);

    unsigned ph = 0;
    #pragma unroll 1
    for (int t = 0; t < TT; t++) {
        const float* wxt = g_WX + (size_t)t * BATCH * DD;
        #pragma unroll 1
        for (int it = 0; it < 5; it++) {
            #pragma unroll 1
            for (int p3 = 0; p3 < 3; p3++) {
                const float* Ain = (p3 == 0) ? g_A0 : (p3 == 1) ? g_A1 : g_A2;
                const float2* sWm = (p3 == 0) ? sW1 : (p3 == 1) ? sW2 : sW3;

                mm_partial(Ain, kbase, sWm, sA, red, bid);
                ph++;
                if (tid == 0) rel_store(&g_pflag[bid*32], pbase + ph);
                if (tid < 4)  acq_poll(&g_pflag[(g*4 + tid)*32], pbase + ph);
                __syncthreads();

                // combine this CTA's stripe: sum 4 partials
                float2 sum = make_float2(0.f, 0.f);
                #pragma unroll
                for (int sp = 0; sp < 4; sp++) {
                    const float2 p = __ldcg((const float2*)&g_part[(size_t)(g*4 + sp)*2048 + gm*32 + cc]);
                    sum.x += p.x; sum.y += p.y;
                }

                if (p3 == 0) {
                    const float2 wx2 = __ldg((const float2*)&wxt[aidx]);
                    float2 o;
                    o.x = elu_f(sum.x + bh.x + wx2.x);
                    o.y = elu_f(sum.y + bh.y + wx2.y);
                    __stcg((float2*)&g_A1[aidx], o);
                } else if (p3 == 1) {
                    float2 o;
                    o.x = elu_f(sum.x + bb2.x);
                    o.y = elu_f(sum.y + bb2.y);
                    __stcg((float2*)&g_A2[aidx], o);
                } else {
                    const float eta = e5[it];
                    const float fn0 = elu_f(sum.x + bb3.x);
                    const float fn1 = elu_f(sum.y + bb3.y);
                    const float h0n = sh_h[o0]   + eta * (fn0 - sh_hp[o0]);
                    const float h1n = sh_h[o0+1] + eta * (fn1 - sh_hp[o0+1]);
                    sh_h[o0] = h0n; sh_h[o0+1] = h1n;
                    float2 hp;
                    if (it == 4) {
                        sh_h0[o0] = h0n; sh_h0[o0+1] = h1n;
                        hp.x = 2.f*h0n; hp.y = 2.f*h1n;
                        *(float2*)&g_H[(size_t)t*BATCH*DD + aidx] = make_float2(h0n, h1n);
                    } else {
                        hp.x = h0n + sh_h0[o0]; hp.y = h1n + sh_h0[o0+1];
                    }
                    sh_hp[o0] = hp.x; sh_hp[o0+1] = hp.y;
                    __stcg((float2*)&g_A0[aidx], hp);
                }

                __syncthreads();
                if (tid == 0) rel_store(&g_aflag[bid*32], abase + 1 + ph);
                if (tid < NCTA) acq_poll(&g_aflag[tid*32], abase + 1 + ph);
                __syncthreads();
            }
        }
    }
}

// ---------------- parallel tiled GEMM: C = A @ W^T + bias ----------------
#define ASTRIDE 132
#define PAR_SMEM_BYTES (2*64*ASTRIDE*4)

__global__ void __launch_bounds__(256, 2) gemm64(const float* __restrict__ A,
                                                 const float* __restrict__ Wm,
                                                 const float* __restrict__ bias,
                                                 float* __restrict__ C)
{
    extern __shared__ float smp[];
    float* sA = smp;
    float* sB = smp + 64*ASTRIDE;

    const int tid  = threadIdx.x;
    const int warp = tid >> 5, lane = tid & 31;
    const int mh = warp & 1, nq = warp >> 1;
    const int mlane = lane >> 2, nlane = lane & 3;
    const int mbase = blockIdx.y * 64, nbase = blockIdx.x * 64;

    ull acc[4][4];
    #pragma unroll
    for (int i = 0; i < 4; i++)
        #pragma unroll
        for (int j = 0; j < 4; j++) acc[i][j] = 0ull;

    #pragma unroll 1
    for (int c = 0; c < 8; c++) {
        if (c) __syncthreads();
        #pragma unroll
        for (int p = 0; p < 8; p++) {
            const int row = p*8 + warp;
            *(ulonglong2*)&sA[row*ASTRIDE + lane*4] =
                __ldg((const ulonglong2*)(A  + (size_t)(mbase+row)*DD + c*128 + lane*4));
            *(ulonglong2*)&sB[row*ASTRIDE + lane*4] =
                __ldg((const ulonglong2*)(Wm + (size_t)(nbase+row)*DD + c*128 + lane*4));
        }
        __syncthreads();
        #pragma unroll 4
        for (int q = 0; q < 32; q++) {
            const int k0 = q*4;
            ulonglong2 a[4], w[4];
            #pragma unroll
            for (int i = 0; i < 4; i++)
                a[i] = *(const ulonglong2*)&sA[(mh*32 + i*8 + mlane)*ASTRIDE + k0];
            #pragma unroll
            for (int j = 0; j < 4; j++)
                w[j] = *(const ulonglong2*)&sB[(nq*16 + j*4 + nlane)*ASTRIDE + k0];
            #pragma unroll
            for (int i = 0; i < 4; i++)
                #pragma unroll
                for (int j = 0; j < 4; j++) {
                    ffma2(acc[i][j], a[i].x, w[j].x);
                    ffma2(acc[i][j], a[i].y, w[j].y);
                }
        }
    }
    #pragma unroll
    for (int i = 0; i < 4; i++)
        #pragma unroll
        for (int j = 0; j < 4; j++) {
            const int m = mbase + mh*32 + i*8 + mlane;
            const int n = nbase + nq*16 + j*4 + nlane;
            C[(size_t)m*DD + n] = hsum2(acc[i][j]) + __ldg(&bias[n]);
        }
}

// ---------------- transposes ----------------
__global__ void transpose_x(const float* __restrict__ x)
{
    __shared__ float tile[32][33];
    const int b  = blockIdx.z;
    const int k0 = blockIdx.y * 32;
    const int t0 = blockIdx.x * 32;
    const int tx = threadIdx.x, ty = threadIdx.y;

    for (int kk = ty; kk < 32; kk += 8) {
        int t = t0 + tx;
        tile[kk][tx] = (t < TT) ? x[(size_t)b*DD*TT + (size_t)(k0 + kk)*TT + t] : 0.f;
    }
    __syncthreads();
    for (int tl = ty; tl < 32; tl += 8) {
        int t = t0 + tl;
        if (t < TT)
            g_xT[((size_t)t*BATCH + b)*DD + k0 + tx] = tile[tx][tl];
    }
}

__global__ void transpose_y(float* __restrict__ out)
{
    __shared__ float tile[32][33];
    const int b  = blockIdx.z;
    const int n0 = blockIdx.y * 32;
    const int t0 = blockIdx.x * 32;
    const int tx = threadIdx.x, ty = threadIdx.y;

    for (int tl = ty; tl < 32; tl += 8) {
        int t = t0 + tl;
        tile[tl][tx] = (t < TT) ? g_Y[((size_t)t*BATCH + b)*DD + n0 + tx] : 0.f;
    }
    __syncthreads();
    for (int nn = ty; nn < 32; nn += 8) {
        int t = t0 + tx;
        if (t < TT)
            out[(size_t)b*DD*TT + (size_t)(n0 + nn)*TT + t] = tile[tx][nn];
    }
}

// ---------------- launch ----------------
extern "C" void kernel_launch(void* const* d_in, const int* in_sizes, int n_in,
                              void* d_out, int out_size)
{
    (void)in_sizes; (void)n_in; (void)out_size;
    const float* x     = (const float*)d_in[0];
    const float* W_in  = (const float*)d_in[1];
    const float* b_in  = (const float*)d_in[2];
    const float* W_hid = (const float*)d_in[3];
    const float* b_hid = (const float*)d_in[4];
    const float* W2    = (const float*)d_in[5];
    const float* b2    = (const float*)d_in[6];
    const float* W3    = (const float*)d_in[7];
    const float* b3    = (const float*)d_in[8];
    const float* W_out = (const float*)d_in[9];
    const float* b_out = (const float*)d_in[10];
    const float* etas  = (const float*)d_in[11];
    float* out = (float*)d_out;

    cudaFuncSetAttribute(ernn_seq, cudaFuncAttributeMaxDynamicSharedMemorySize, SEQ_BYTES);
    cudaFuncSetAttribute(gemm64,   cudaFuncAttributeMaxDynamicSharedMemorySize, PAR_SMEM_BYTES);

    dim3 tb(32, 8);
    dim3 tgx((TT + 31)/32, DD/32, BATCH);
    transpose_x<<<tgx, tb>>>(x);

    {
        float* gWX; float* gxT;
        cudaGetSymbolAddress((void**)&gWX, g_WX);
        cudaGetSymbolAddress((void**)&gxT, g_xT);
        dim3 gg(DD/64, TB/64);
        gemm64<<<gg, 256, PAR_SMEM_BYTES>>>(gxT, W_in, b_in, gWX);
    }

    ernn_seq<<<NCTA, 256, SEQ_BYTES>>>(W_hid, b_hid, W2, b2, W3, b3, etas);

    {
        float* gH; float* gY;
        cudaGetSymbolAddress((void**)&gH, g_H);
        cudaGetSymbolAddress((void**)&gY, g_Y);
        dim3 gg(DD/64, TB/64);
        gemm64<<<gg, 256, PAR_SMEM_BYTES>>>(gH, W_out, b_out, gY);
    }

    dim3 tgy((TT + 31)/32, DD/32, BATCH);
    transpose_y<<<tgy, tb>>>(out);
}

// round 17
// speedup vs baseline: 1.6728x; 1.3132x over previous
#include <cuda_runtime.h>
#include <cooperative_groups.h>
#include <cstdint>

namespace cg = cooperative_groups;

#define DD 1024
#define BATCH 64
#define TT 200
#define TB (TT*BATCH)
#define NCTA 128

typedef unsigned long long ull;

// ---------------- scratch (static __device__, no allocations) ----------------
__device__ float g_xT[TB*DD];      // x transposed: [t][b][k]
__device__ float g_WX[TB*DD];      // wx for all timesteps
__device__ float g_H [TB*DD];      // h_t for all timesteps
__device__ float g_Y [TB*DD];      // y before final transpose
__device__ float g_A0[BATCH*DD];   // h+h0  (GEMM input P1)
__device__ float g_A1[BATCH*DD];   // F1    (GEMM input P2)
__device__ float g_A2[BATCH*DD];   // T2    (GEMM input P3)
__device__ unsigned g_aflag[NCTA*32];   // per-CTA phase flags (128B apart)

// ---------------- helpers ----------------
__device__ __forceinline__ void ffma2(ull& d, ull a, ull b) {
    asm("fma.rn.f32x2 %0, %1, %2, %0;" : "+l"(d) : "l"(a), "l"(b));
}
__device__ __forceinline__ float hsum2(ull v) {
    float lo, hi;
    asm("mov.b64 {%0,%1}, %2;" : "=f"(lo), "=f"(hi) : "l"(v));
    return lo + hi;
}
__device__ __forceinline__ float elu_f(float x) { return x > 0.f ? x : expm1f(x); }

__device__ __forceinline__ void cp16(float* dst_smem, const float* src) {
    unsigned s = (unsigned)__cvta_generic_to_shared(dst_smem);
    asm volatile("cp.async.cg.shared.global [%0], [%1], 16;" :: "r"(s), "l"(src));
}
__device__ __forceinline__ void cp_commit() {
    asm volatile("cp.async.commit_group;");
}
__device__ __forceinline__ void rel_store(unsigned* p, unsigned v) {
    asm volatile("st.release.gpu.global.u32 [%0], %1;" :: "l"(p), "r"(v) : "memory");
}
__device__ __forceinline__ void acq_poll(const unsigned* p, unsigned target) {
    unsigned v;
    do {
        asm volatile("ld.acquire.gpu.global.u32 %0, [%1];" : "=r"(v) : "l"(p) : "memory");
    } while ((int)(v - target) < 0);
}

// ---------------- seq smem layout (floats) ----------------
// sW: 3 x [128 kpairs][34] float2 = 26112 floats
// sA: [64][268]                   = 17152
// red: [64][36]                   = 2304
// comb: [2 parity][4 prod][16][36]= 4608
// state: 3 x 512                  = 1536
#define SWF2      4352
#define SASTRIDE  268
#define OFF_SA    26112
#define OFF_RED   (OFF_SA + 64*SASTRIDE)   // 43264
#define OFF_COMB  (OFF_RED + 2304)         // 45568
#define OFF_H     (OFF_COMB + 4608)        // 50176
#define SEQ_FLOATS (OFF_H + 3*512)         // 51712
#define SEQ_BYTES  (SEQ_FLOATS*4)          // 206848

// ---------------- per-phase GEMM + cluster exchange ----------------
// Computes partial[64][32] = A[64][kbase..+255] @ Wslice[32][256]^T, exchanges
// stripes via DSMEM within the 4-CTA cluster, returns combined float2 for this
// thread's two outputs (row s*16 + (tid>>4), cols nbg + (tid&15)*2 .. +1).
__device__ __forceinline__ float2 mm_exchange(
    const float* __restrict__ Ag, int kbase, const float2* __restrict__ sWm,
    float* __restrict__ sA, float* __restrict__ red, float* __restrict__ comb,
    cg::cluster_group& clu, int myrank, unsigned par)
{
    const int tid  = threadIdx.x;
    const int warp = tid >> 5, lane = tid & 31;
    const int wq = warp & 3, wh = warp >> 2;
    const int mg = lane & 7, ng = (lane >> 3) & 1;
    const int kss4 = (lane >> 4) * 4;
    const int n0 = wq*8 + ng*4;   // col base (float2 idx in sW row; float idx in comb)

    // stage: two half-waves of cp.async (k 0..127 then 128..255), both issued now
    #pragma unroll
    for (int r = 0; r < 8; r++) {
        const int id = r*256 + tid, row = id >> 5, u = id & 31;
        cp16(sA + row*SASTRIDE + u*4, Ag + row*DD + kbase + u*4);
    }
    cp_commit();
    #pragma unroll
    for (int r = 0; r < 8; r++) {
        const int id = r*256 + tid, row = id >> 5, u = id & 31;
        cp16(sA + row*SASTRIDE + 128 + u*4, Ag + row*DD + kbase + 128 + u*4);
    }
    cp_commit();

    ull acc[8][4];
    #pragma unroll
    for (int i = 0; i < 8; i++)
        #pragma unroll
        for (int j = 0; j < 4; j++) acc[i][j] = 0ull;

    asm volatile("cp.async.wait_group 1;");
    __syncthreads();

    #pragma unroll 1
    for (int h = 0; h < 2; h++) {
        if (h == 1) { asm volatile("cp.async.wait_group 0;"); __syncthreads(); }
        #pragma unroll
        for (int q = 0; q < 8; q++) {
            const int kc = h*128 + q*16 + wh*8 + kss4;
            ulonglong2 av[8];
            #pragma unroll
            for (int i = 0; i < 8; i++)
                av[i] = *(const ulonglong2*)(sA + (i*8 + mg)*SASTRIDE + kc);

            const int kpl = kc >> 1;
            const ulonglong2 wa0 = *(const ulonglong2*)(sWm + kpl*34 + n0);
            const ulonglong2 wa1 = *(const ulonglong2*)(sWm + kpl*34 + n0 + 2);
            const ulonglong2 wb0 = *(const ulonglong2*)(sWm + (kpl+1)*34 + n0);
            const ulonglong2 wb1 = *(const ulonglong2*)(sWm + (kpl+1)*34 + n0 + 2);

            #pragma unroll
            for (int i = 0; i < 8; i++) {
                ffma2(acc[i][0], av[i].x, wa0.x);
                ffma2(acc[i][0], av[i].y, wb0.x);
                ffma2(acc[i][1], av[i].x, wa0.y);
                ffma2(acc[i][1], av[i].y, wb0.y);
                ffma2(acc[i][2], av[i].x, wa1.x);
                ffma2(acc[i][2], av[i].y, wb1.x);
                ffma2(acc[i][3], av[i].x, wa1.y);
                ffma2(acc[i][3], av[i].y, wb1.y);
            }
        }
    }

    // reduce kss (shfl) then wh (smem); holders = wh==0, lane<16
    float v[32];
    #pragma unroll
    for (int i = 0; i < 8; i++)
        #pragma unroll
        for (int j = 0; j < 4; j++) v[i*4+j] = hsum2(acc[i][j]);
    #pragma unroll
    for (int e = 0; e < 32; e++)
        v[e] += __shfl_xor_sync(0xffffffffu, v[e], 16);

    if (wh == 1 && lane < 16) {
        float* r = red + (wq*16 + lane)*36;
        #pragma unroll
        for (int b = 0; b < 8; b++)
            *(float4*)&r[b*4] = make_float4(v[b*4], v[b*4+1], v[b*4+2], v[b*4+3]);
    }
    __syncthreads();

    if (wh == 0 && lane < 16) {
        const float* r = red + (wq*16 + lane)*36;
        #pragma unroll
        for (int b = 0; b < 8; b++) {
            float4 p = *(const float4*)&r[b*4];
            v[b*4] += p.x; v[b*4+1] += p.y; v[b*4+2] += p.z; v[b*4+3] += p.w;
        }
        // DSMEM scatter: rows i*8+mg -> dest rank i>>1, local row (i&1)*8+mg
        #pragma unroll
        for (int i = 0; i < 8; i++) {
            const int rk = i >> 1;
            const int lrow = (i & 1)*8 + mg;
            float* dstbase = clu.map_shared_rank(comb, rk);
            *(float4*)(dstbase + par*2304 + (myrank*16 + lrow)*36 + n0) =
                make_float4(v[i*4], v[i*4+1], v[i*4+2], v[i*4+3]);
        }
    }
    clu.sync();

    // combine own 16x32 stripe from the 4 producer slots
    const int cm = tid >> 4, cc = (tid & 15) * 2;
    float2 sum = make_float2(0.f, 0.f);
    #pragma unroll
    for (int sp = 0; sp < 4; sp++) {
        const float2 p = *(const float2*)(comb + par*2304 + (sp*16 + cm)*36 + cc);
        sum.x += p.x; sum.y += p.y;
    }
    return sum;
}

// ---------------- persistent sequential kernel ----------------
__global__ void __launch_bounds__(256, 1) __cluster_dims__(4, 1, 1) ernn_seq(
    const float* __restrict__ Whid, const float* __restrict__ bhid,
    const float* __restrict__ Wm2,  const float* __restrict__ b2,
    const float* __restrict__ Wm3,  const float* __restrict__ b3,
    const float* __restrict__ etas)
{
    extern __shared__ float sm[];
    float2* sW1 = (float2*)sm;
    float2* sW2 = sW1 + SWF2;
    float2* sW3 = sW2 + SWF2;
    float*  sA   = sm + OFF_SA;
    float*  red  = sm + OFF_RED;
    float*  comb = sm + OFF_COMB;
    float*  sh_h  = sm + OFF_H;
    float*  sh_h0 = sh_h + 512;
    float*  sh_hp = sh_h0 + 512;

    cg::cluster_group clu = cg::this_cluster();
    const int tid = threadIdx.x;
    const int bid = blockIdx.x;
    const int g = bid >> 2;
    const int s = clu.block_rank();        // == bid & 3 for (4,1,1) clusters
    const int nbg = g * 32;
    const int kbase = s * 256;

    unsigned abase;
    asm volatile("ld.global.u32 %0, [%1];" : "=r"(abase) : "l"(&g_aflag[bid*32]));

    // weight slices: sW[kp*34+n] = {W[nbg+n][kbase+2kp], W[nbg+n][kbase+2kp+1]}
    for (int idx = tid; idx < 128*32; idx += 256) {
        const int kp = idx >> 5, n = idx & 31;
        sW1[kp*34 + n] = __ldg((const float2*)&Whid[(size_t)(nbg+n)*DD + kbase + 2*kp]);
        sW2[kp*34 + n] = __ldg((const float2*)&Wm2 [(size_t)(nbg+n)*DD + kbase + 2*kp]);
        sW3[kp*34 + n] = __ldg((const float2*)&Wm3 [(size_t)(nbg+n)*DD + kbase + 2*kp]);
    }

    // combine-stripe coordinates: rows s*16..+15, cols nbg..+31
    const int cm = tid >> 4;
    const int cc = (tid & 15) * 2;
    const int gm = s*16 + cm;
    const int aidx = gm*DD + nbg + cc;
    const int o0 = tid * 2;

    // init state + A0 stripe
    sh_h[o0] = 0.f; sh_h[o0+1] = 0.f;
    sh_h0[o0] = 0.f; sh_h0[o0+1] = 0.f;
    sh_hp[o0] = 0.f; sh_hp[o0+1] = 0.f;
    __stcg((float2*)&g_A0[aidx], make_float2(0.f, 0.f));
    __syncthreads();
    if (tid == 0) rel_store(&g_aflag[bid*32], abase + 1);
    if (tid < NCTA) acq_poll(&g_aflag[tid*32], abase + 1);
    __syncthreads();
    unsigned fl = abase + 1;

    // epilogue constants
    const float2 bh  = __ldg((const float2*)&bhid[nbg + cc]);
    const float2 bb2 = __ldg((const float2*)&b2[nbg + cc]);
    const float2 bb3 = __ldg((const float2*)&b3[nbg + cc]);
    float e5[5];
    #pragma unroll
    for (int k = 0; k < 5; k++) e5[k] = __ldg(&etas[k]);

    #pragma unroll 1
    for (int t = 0; t < TT; t++) {
        const float2 wx2 = __ldg((const float2*)&g_WX[(size_t)t*BATCH*DD + aidx]);
        #pragma unroll 1
        for (int it = 0; it < 5; it++) {
            #pragma unroll 1
            for (int p3 = 0; p3 < 3; p3++) {
                const float* Ain  = (p3 == 0) ? g_A0 : (p3 == 1) ? g_A1 : g_A2;
                const float2* sWm = (p3 == 0) ? sW1 : (p3 == 1) ? sW2 : sW3;

                // wait for this phase's activation producers (32 contiguous CTAs)
                if (tid < 32) acq_poll(&g_aflag[(32*s + tid)*32], fl);
                __syncthreads();

                float2 r = mm_exchange(Ain, kbase, sWm, sA, red, comb, clu, s, fl & 1);

                if (p3 == 0) {
                    float2 o;
                    o.x = elu_f(r.x + bh.x + wx2.x);
                    o.y = elu_f(r.y + bh.y + wx2.y);
                    __stcg((float2*)&g_A1[aidx], o);
                } else if (p3 == 1) {
                    float2 o;
                    o.x = elu_f(r.x + bb2.x);
                    o.y = elu_f(r.y + bb2.y);
                    __stcg((float2*)&g_A2[aidx], o);
                } else {
                    const float eta = e5[it];
                    const float fn0 = elu_f(r.x + bb3.x);
                    const float fn1 = elu_f(r.y + bb3.y);
                    const float h0n = sh_h[o0]   + eta * (fn0 - sh_hp[o0]);
                    const float h1n = sh_h[o0+1] + eta * (fn1 - sh_hp[o0+1]);
                    sh_h[o0] = h0n; sh_h[o0+1] = h1n;
                    float2 hp;
                    if (it == 4) {
                        sh_h0[o0] = h0n; sh_h0[o0+1] = h1n;
                        hp.x = 2.f*h0n; hp.y = 2.f*h1n;
                        *(float2*)&g_H[(size_t)t*BATCH*DD + aidx] = make_float2(h0n, h1n);
                    } else {
                        hp.x = h0n + sh_h0[o0]; hp.y = h1n + sh_h0[o0+1];
                    }
                    sh_hp[o0] = hp.x; sh_hp[o0+1] = hp.y;
                    __stcg((float2*)&g_A0[aidx], hp);
                }

                __syncthreads();
                if (tid == 0) rel_store(&g_aflag[bid*32], fl + 1);
                fl++;
            }
        }
    }
}

// ---------------- parallel tiled GEMM: C = A @ W^T + bias ----------------
#define ASTRIDE 132
#define PAR_SMEM_BYTES (2*64*ASTRIDE*4)

__global__ void __launch_bounds__(256, 2) gemm64(const float* __restrict__ A,
                                                 const float* __restrict__ Wm,
                                                 const float* __restrict__ bias,
                                                 float* __restrict__ C)
{
    extern __shared__ float smp[];
    float* sA = smp;
    float* sB = smp + 64*ASTRIDE;

    const int tid  = threadIdx.x;
    const int warp = tid >> 5, lane = tid & 31;
    const int mh = warp & 1, nq = warp >> 1;
    const int mlane = lane >> 2, nlane = lane & 3;
    const int mbase = blockIdx.y * 64, nbase = blockIdx.x * 64;

    ull acc[4][4];
    #pragma unroll
    for (int i = 0; i < 4; i++)
        #pragma unroll
        for (int j = 0; j < 4; j++) acc[i][j] = 0ull;

    #pragma unroll 1
    for (int c = 0; c < 8; c++) {
        if (c) __syncthreads();
        #pragma unroll
        for (int p = 0; p < 8; p++) {
            const int row = p*8 + warp;
            *(ulonglong2*)&sA[row*ASTRIDE + lane*4] =
                __ldg((const ulonglong2*)(A  + (size_t)(mbase+row)*DD + c*128 + lane*4));
            *(ulonglong2*)&sB[row*ASTRIDE + lane*4] =
                __ldg((const ulonglong2*)(Wm + (size_t)(nbase+row)*DD + c*128 + lane*4));
        }
        __syncthreads();
        #pragma unroll 4
        for (int q = 0; q < 32; q++) {
            const int k0 = q*4;
            ulonglong2 a[4], w[4];
            #pragma unroll
            for (int i = 0; i < 4; i++)
                a[i] = *(const ulonglong2*)&sA[(mh*32 + i*8 + mlane)*ASTRIDE + k0];
            #pragma unroll
            for (int j = 0; j < 4; j++)
                w[j] = *(const ulonglong2*)&sB[(nq*16 + j*4 + nlane)*ASTRIDE + k0];
            #pragma unroll
            for (int i = 0; i < 4; i++)
                #pragma unroll
                for (int j = 0; j < 4; j++) {
                    ffma2(acc[i][j], a[i].x, w[j].x);
                    ffma2(acc[i][j], a[i].y, w[j].y);
                }
        }
    }
    #pragma unroll
    for (int i = 0; i < 4; i++)
        #pragma unroll
        for (int j = 0; j < 4; j++) {
            const int m = mbase + mh*32 + i*8 + mlane;
            const int n = nbase + nq*16 + j*4 + nlane;
            C[(size_t)m*DD + n] = hsum2(acc[i][j]) + __ldg(&bias[n]);
        }
}

// ---------------- transposes ----------------
__global__ void transpose_x(const float* __restrict__ x)
{
    __shared__ float tile[32][33];
    const int b  = blockIdx.z;
    const int k0 = blockIdx.y * 32;
    const int t0 = blockIdx.x * 32;
    const int tx = threadIdx.x, ty = threadIdx.y;

    for (int kk = ty; kk < 32; kk += 8) {
        int t = t0 + tx;
        tile[kk][tx] = (t < TT) ? x[(size_t)b*DD*TT + (size_t)(k0 + kk)*TT + t] : 0.f;
    }
    __syncthreads();
    for (int tl = ty; tl < 32; tl += 8) {
        int t = t0 + tl;
        if (t < TT)
            g_xT[((size_t)t*BATCH + b)*DD + k0 + tx] = tile[tx][tl];
    }
}

__global__ void transpose_y(float* __restrict__ out)
{
    __shared__ float tile[32][33];
    const int b  = blockIdx.z;
    const int n0 = blockIdx.y * 32;
    const int t0 = blockIdx.x * 32;
    const int tx = threadIdx.x, ty = threadIdx.y;

    for (int tl = ty; tl < 32; tl += 8) {
        int t = t0 + tl;
        tile[tl][tx] = (t < TT) ? g_Y[((size_t)t*BATCH + b)*DD + n0 + tx] : 0.f;
    }
    __syncthreads();
    for (int nn = ty; nn < 32; nn += 8) {
        int t = t0 + tx;
        if (t < TT)
            out[(size_t)b*DD*TT + (size_t)(n0 + nn)*TT + t] = tile[tx][nn];
    }
}

// ---------------- launch ----------------
extern "C" void kernel_launch(void* const* d_in, const int* in_sizes, int n_in,
                              void* d_out, int out_size)
{
    (void)in_sizes; (void)n_in; (void)out_size;
    const float* x     = (const float*)d_in[0];
    const float* W_in  = (const float*)d_in[1];
    const float* b_in  = (const float*)d_in[2];
    const float* W_hid = (const float*)d_in[3];
    const float* b_hid = (const float*)d_in[4];
    const float* W2    = (const float*)d_in[5];
    const float* b2    = (const float*)d_in[6];
    const float* W3    = (const float*)d_in[7];
    const float* b3    = (const float*)d_in[8];
    const float* W_out = (const float*)d_in[9];
    const float* b_out = (const float*)d_in[10];
    const float* etas  = (const float*)d_in[11];
    float* out = (float*)d_out;

    cudaFuncSetAttribute(ernn_seq, cudaFuncAttributeMaxDynamicSharedMemorySize, SEQ_BYTES);
    cudaFuncSetAttribute(gemm64,   cudaFuncAttributeMaxDynamicSharedMemorySize, PAR_SMEM_BYTES);

    dim3 tb(32, 8);
    dim3 tgx((TT + 31)/32, DD/32, BATCH);
    transpose_x<<<tgx, tb>>>(x);

    {
        float* gWX; float* gxT;
        cudaGetSymbolAddress((void**)&gWX, g_WX);
        cudaGetSymbolAddress((void**)&gxT, g_xT);
        dim3 gg(DD/64, TB/64);
        gemm64<<<gg, 256, PAR_SMEM_BYTES>>>(gxT, W_in, b_in, gWX);
    }

    ernn_seq<<<NCTA, 256, SEQ_BYTES>>>(W_hid, b_hid, W2, b2, W3, b3, etas);

    {
        float* gH; float* gY;
        cudaGetSymbolAddress((void**)&gH, g_H);
        cudaGetSymbolAddress((void**)&gY, g_Y);
        dim3 gg(DD/64, TB/64);
        gemm64<<<gg, 256, PAR_SMEM_BYTES>>>(gH, W_out, b_out, gY);
    }

    dim3 tgy((TT + 31)/32, DD/32, BATCH);
    transpose_y<<<tgy, tb>>>(out);
}